// round 17
// baseline (speedup 1.0000x reference)
#include <cuda_runtime.h>
#include <cuda_bf16.h>
#include <cuda_fp16.h>
#include <math.h>
#include <stdint.h>

#define NN 100000
#define NE 1600000
#define HD 128
#define EPSV 1e-5f
#define AROW 68   // uint32 stride per row (64 pairs + 4 pad)

// ---------------- scratch ----------------
__device__ int   g_deg[NN];
__device__ int   g_fill[NN];
__device__ int   g_off[NN + 1];
__device__ float g_dinv[NN];
__device__ int   g_csrc[NE];
__device__ float g_bufA[(size_t)NN * HD];          // fp32 gemm input (agg output)
__device__ uint32_t g_h16[(size_t)NN * 64];        // fp16x2 prescaled gemm output (agg gather src)
__device__ float g_Wc[HD * 2];
__device__ float g_bc[2];
// B fragments (hi/lo bf16x2 pairs), order: [mat 3][ntile 16][k 8][lane 32]
__device__ uint2 g_bH[3][4096];
__device__ uint2 g_bL[3][4096];

// ---------------- graph preprocessing ----------------
__global__ void k_zero() {
    int i = blockIdx.x * blockDim.x + threadIdx.x;
    if (i < NN) { g_deg[i] = 0; g_fill[i] = 0; }
}

__global__ void k_count(const int* __restrict__ dst) {
    int i = blockIdx.x * blockDim.x + threadIdx.x;
    if (i < NE) atomicAdd(&g_deg[dst[i]], 1);
}

__global__ void k_scan() {
    __shared__ int ss[1024];
    const int T = 1024;
    const int CH = (NN + T - 1) / T;
    int t = threadIdx.x;
    int lo = t * CH; if (lo > NN) lo = NN;
    int hi = lo + CH; if (hi > NN) hi = NN;
    int s = 0;
    for (int i = lo; i < hi; i++) s += g_deg[i];
    ss[t] = s;
    __syncthreads();
    for (int d = 1; d < T; d <<= 1) {
        int v = (t >= d) ? ss[t - d] : 0;
        __syncthreads();
        ss[t] += v;
        __syncthreads();
    }
    int run = (t == 0) ? 0 : ss[t - 1];
    for (int i = lo; i < hi; i++) {
        g_off[i] = run;
        int dg = g_deg[i];
        run += dg;
        g_dinv[i] = rsqrtf((float)(dg + 1));
    }
    if (t == T - 1) g_off[NN] = run;
}

__global__ void k_scatter(const int* __restrict__ src, const int* __restrict__ dst) {
    int i = blockIdx.x * blockDim.x + threadIdx.x;
    if (i < NE) {
        int d = dst[i];
        int p = g_off[d] + atomicAdd(&g_fill[d], 1);
        g_csrc[p] = src[i];
    }
}

// ---------------- bf16 split helpers ----------------
__device__ __forceinline__ uint32_t pack_bf16_hi(float a, float b) {
    __nv_bfloat162 p = __floats2bfloat162_rn(a, b);
    return *(uint32_t*)&p;
}
__device__ __forceinline__ float bf16_resid(float x) {
    return x - __bfloat162float(__float2bfloat16_rn(x));
}
__device__ __forceinline__ void mma_bf16(float* d, const uint32_t* a, uint32_t b0, uint32_t b1) {
    asm volatile(
        "mma.sync.aligned.m16n8k16.row.col.f32.bf16.bf16.f32 "
        "{%0,%1,%2,%3}, {%4,%5,%6,%7}, {%8,%9}, {%0,%1,%2,%3};"
        : "+f"(d[0]), "+f"(d[1]), "+f"(d[2]), "+f"(d[3])
        : "r"(a[0]), "r"(a[1]), "r"(a[2]), "r"(a[3]), "r"(b0), "r"(b1));
}
__device__ __forceinline__ float2 h2f(uint32_t u) {
    __half2 h = *(__half2*)&u;
    return __half22float2(h);
}

// precompute B fragments for all 3 matrices in one launch
__global__ void k_bfrag_all(const float* __restrict__ W1, const float* __restrict__ W2,
                            const float* __restrict__ W3) {
    int sg = blockIdx.x * blockDim.x + threadIdx.x;
    if (sg >= 3 * 4096) return;
    int mat = sg >> 12;
    int s = sg & 4095;
    const float* W = (mat == 0) ? W1 : (mat == 1) ? W2 : W3;
    int ti = s >> 8;
    int k  = (s >> 5) & 7;
    int ln = s & 31;
    int g = ln >> 2, tt = ln & 3;
    int c = ti * 8 + g;
    int r0 = k * 16 + 2 * tt;
    int r1 = k * 16 + 2 * tt + 8;
    float v00 = W[r0 * 128 + c],       v01 = W[(r0 + 1) * 128 + c];
    float v10 = W[r1 * 128 + c],       v11 = W[(r1 + 1) * 128 + c];
    g_bH[mat][s] = make_uint2(pack_bf16_hi(v00, v01), pack_bf16_hi(v10, v11));
    g_bL[mat][s] = make_uint2(pack_bf16_hi(bf16_resid(v00), bf16_resid(v01)),
                              pack_bf16_hi(bf16_resid(v10), bf16_resid(v11)));
}

// ---------------- tensor-core bf16 (3-term split) GEMM ----------------
// out: prescaled fp16x2 (row r multiplied by g_dinv[r])
__global__ __launch_bounds__(256, 2) void gemm_tc(const float* __restrict__ A,
                                                  const uint2* __restrict__ bh,
                                                  const uint2* __restrict__ bl,
                                                  uint32_t* __restrict__ C16, int M) {
    extern __shared__ uint32_t smU[];
    uint32_t* aHi = smU;                   // [128][AROW]
    uint32_t* aLo = smU + 128 * AROW;      // [128][AROW]
    int tid = threadIdx.x;
    int bm = blockIdx.x * 128;

    // staging: load float4 rows coalesced, convert ONCE to bf16x2 hi/lo pairs
    for (int s = tid; s < 128 * 32; s += 256) {
        int row = s >> 5, q = s & 31;
        int gr = bm + row;
        float4 v = (gr < M) ? *(const float4*)(A + (size_t)gr * 128 + q * 4)
                            : make_float4(0.f, 0.f, 0.f, 0.f);
        uint2 hi = make_uint2(pack_bf16_hi(v.x, v.y), pack_bf16_hi(v.z, v.w));
        uint2 lo = make_uint2(pack_bf16_hi(bf16_resid(v.x), bf16_resid(v.y)),
                              pack_bf16_hi(bf16_resid(v.z), bf16_resid(v.w)));
        *(uint2*)&aHi[row * AROW + q * 2] = hi;
        *(uint2*)&aLo[row * AROW + q * 2] = lo;
    }
    __syncthreads();

    int wid = tid >> 5, ln = tid & 31;
    int wm = wid & 3;
    int wn = wid >> 2;
    int g = ln >> 2, tt = ln & 3;

    float acc[2][8][4] = {};

#pragma unroll
    for (int k = 0; k < 8; k++) {
        uint32_t ah[2][4], al[2][4];
#pragma unroll
        for (int mi = 0; mi < 2; mi++) {
            int row0 = (wm * 2 + mi) * 16 + g;
            int base0 = row0 * AROW + k * 8 + tt;
            int base1 = (row0 + 8) * AROW + k * 8 + tt;
            ah[mi][0] = aHi[base0];
            ah[mi][1] = aHi[base1];
            ah[mi][2] = aHi[base0 + 4];
            ah[mi][3] = aHi[base1 + 4];
            al[mi][0] = aLo[base0];
            al[mi][1] = aLo[base1];
            al[mi][2] = aLo[base0 + 4];
            al[mi][3] = aLo[base1 + 4];
        }
#pragma unroll
        for (int ti = 0; ti < 8; ti++) {
            int idx = ((wn * 8 + ti) * 8 + k) * 32 + ln;
            uint2 H = bh[idx];
            uint2 L = bl[idx];
#pragma unroll
            for (int mi = 0; mi < 2; mi++) {
                mma_bf16(acc[mi][ti], ah[mi], H.x, H.y);
                mma_bf16(acc[mi][ti], al[mi], H.x, H.y);
                mma_bf16(acc[mi][ti], ah[mi], L.x, L.y);
            }
        }
    }

    // epilogue: prescale by dinv[row], store fp16x2
#pragma unroll
    for (int mi = 0; mi < 2; mi++) {
        int row0 = bm + (wm * 2 + mi) * 16 + g;
        int row1 = row0 + 8;
        float w0 = (row0 < M) ? g_dinv[row0] : 0.f;
        float w1 = (row1 < M) ? g_dinv[row1] : 0.f;
#pragma unroll
        for (int ti = 0; ti < 8; ti++) {
            int cidx = (wn * 8 + ti) * 4 + tt;
            if (row0 < M) {
                __half2 h = __floats2half2_rn(acc[mi][ti][0] * w0, acc[mi][ti][1] * w0);
                C16[(size_t)row0 * 64 + cidx] = *(uint32_t*)&h;
            }
            if (row1 < M) {
                __half2 h = __floats2half2_rn(acc[mi][ti][2] * w1, acc[mi][ti][3] * w1);
                C16[(size_t)row1 * 64 + cidx] = *(uint32_t*)&h;
            }
        }
    }
}

// ---------------- aggregation: masked-batch fp16 row sum ----------------
__global__ void k_agg(const uint32_t* __restrict__ lin16, const float* __restrict__ bias,
                      const float* __restrict__ lng, const float* __restrict__ lnb,
                      float* __restrict__ outp, int doLN, float* __restrict__ logp) {
    int gtid = blockIdx.x * blockDim.x + threadIdx.x;
    int node = gtid >> 5;
    if (node >= NN) return;
    int lane = gtid & 31;

    float dn = g_dinv[node];
    // self (already prescaled by dinv[node])
    uint2 su = *(const uint2*)(lin16 + (size_t)node * 64 + lane * 2);
    float2 s0 = h2f(su.x), s1 = h2f(su.y);
    float4 acc = make_float4(s0.x, s0.y, s1.x, s1.y);

    int e0 = g_off[node], e1 = g_off[node + 1];
    // fully predicated batches of 8: loads always issued (clamped addr), adds masked
    for (int e = e0; e < e1; e += 8) {
        int   idx[8];
        float msk[8];
#pragma unroll
        for (int j = 0; j < 8; j++) {
            int ee = e + j;
            bool valid = ee < e1;
            idx[j] = valid ? ee : e0;
            msk[j] = valid ? 1.0f : 0.0f;
        }
        int s_[8];
#pragma unroll
        for (int j = 0; j < 8; j++) s_[j] = g_csrc[idx[j]];
        uint2 u[8];
#pragma unroll
        for (int j = 0; j < 8; j++)
            u[j] = *(const uint2*)(lin16 + (size_t)s_[j] * 64 + lane * 2);
#pragma unroll
        for (int j = 0; j < 8; j++) {
            float2 a0 = h2f(u[j].x), a1 = h2f(u[j].y);
            acc.x += msk[j] * a0.x;
            acc.y += msk[j] * a0.y;
            acc.z += msk[j] * a1.x;
            acc.w += msk[j] * a1.y;
        }
    }
    // final scale by dinv[dst] + bias
    float4 bb = ((const float4*)bias)[lane];
    acc.x = acc.x * dn + bb.x;
    acc.y = acc.y * dn + bb.y;
    acc.z = acc.z * dn + bb.z;
    acc.w = acc.w * dn + bb.w;

    if (doLN) {
        acc.x = fmaxf(acc.x, 0.f); acc.y = fmaxf(acc.y, 0.f);
        acc.z = fmaxf(acc.z, 0.f); acc.w = fmaxf(acc.w, 0.f);
        float s1r = acc.x + acc.y + acc.z + acc.w;
        float s2r = acc.x * acc.x + acc.y * acc.y + acc.z * acc.z + acc.w * acc.w;
#pragma unroll
        for (int o = 16; o > 0; o >>= 1) {
            s1r += __shfl_xor_sync(0xffffffffu, s1r, o);
            s2r += __shfl_xor_sync(0xffffffffu, s2r, o);
        }
        float mu = s1r * (1.0f / HD);
        float var = s2r * (1.0f / HD) - mu * mu;
        float r = rsqrtf(var + EPSV);
        float4 gg = ((const float4*)lng)[lane];
        float4 bl = ((const float4*)lnb)[lane];
        acc.x = (acc.x - mu) * r * gg.x + bl.x;
        acc.y = (acc.y - mu) * r * gg.y + bl.y;
        acc.z = (acc.z - mu) * r * gg.z + bl.z;
        acc.w = (acc.w - mu) * r * gg.w + bl.w;
        ((float4*)(outp + (size_t)node * HD))[lane] = acc;
    } else {
        ((float4*)(outp + (size_t)node * HD))[lane] = acc;
        float4 r = make_float4(fmaxf(acc.x, 0.f), fmaxf(acc.y, 0.f),
                               fmaxf(acc.z, 0.f), fmaxf(acc.w, 0.f));
        const float4* wp = (const float4*)g_Wc;
        float4 wa = wp[lane * 2];
        float4 wb = wp[lane * 2 + 1];
        float l0 = r.x * wa.x + r.y * wa.z + r.z * wb.x + r.w * wb.z;
        float l1 = r.x * wa.y + r.y * wa.w + r.z * wb.y + r.w * wb.w;
#pragma unroll
        for (int o = 16; o > 0; o >>= 1) {
            l0 += __shfl_xor_sync(0xffffffffu, l0, o);
            l1 += __shfl_xor_sync(0xffffffffu, l1, o);
        }
        if (lane == 0) {
            l0 += g_bc[0]; l1 += g_bc[1];
            float m = fmaxf(l0, l1);
            float lse = m + logf(expf(l0 - m) + expf(l1 - m));
            logp[(size_t)node * 2 + 0] = l0 - lse;
            logp[(size_t)node * 2 + 1] = l1 - lse;
        }
    }
}

// ---------------- MLP head collapse ----------------
__global__ void k_compose(const float* __restrict__ mpW1, const float* __restrict__ mpW2,
                          const float* __restrict__ mpb1, const float* __restrict__ mpb2) {
    int t = threadIdx.x;
    int k = t >> 1, c = t & 1;
    float s = 0.f;
    for (int j = 0; j < 128; j++) s += mpW1[k * 128 + j] * mpW2[j * 2 + c];
    g_Wc[k * 2 + c] = s;
    if (t < 2) {
        float sb = 0.f;
        for (int j = 0; j < 128; j++) sb += mpb1[j] * mpW2[j * 2 + t];
        g_bc[t] = sb + mpb2[t];
    }
}

// ---------------- launch ----------------
extern "C" void kernel_launch(void* const* d_in, const int* in_sizes, int n_in,
                              void* d_out, int out_size) {
    const float* x    = (const float*)d_in[0];
    const int*   ei   = (const int*)d_in[1];
    const int*   srcI = ei;
    const int*   dstI = ei + NE;
    const float* W1 = (const float*)d_in[2];
    const float* b1 = (const float*)d_in[3];
    const float* W2 = (const float*)d_in[4];
    const float* b2 = (const float*)d_in[5];
    const float* W3 = (const float*)d_in[6];
    const float* b3 = (const float*)d_in[7];
    const float* ln1g = (const float*)d_in[8];
    const float* ln1b = (const float*)d_in[9];
    const float* ln2g = (const float*)d_in[10];
    const float* ln2b = (const float*)d_in[11];
    const float* mpW1 = (const float*)d_in[12];
    const float* mpb1 = (const float*)d_in[13];
    const float* mpW2 = (const float*)d_in[14];
    const float* mpb2 = (const float*)d_in[15];

    float* out  = (float*)d_out;
    float* emb  = out;
    float* logp = out + (size_t)NN * HD;

    float* bufA;
    uint32_t* h16;
    cudaGetSymbolAddress((void**)&bufA, g_bufA);
    cudaGetSymbolAddress((void**)&h16, g_h16);
    uint2 *bH, *bL;
    cudaGetSymbolAddress((void**)&bH, g_bH);
    cudaGetSymbolAddress((void**)&bL, g_bL);

    int smemSz = 2 * 128 * AROW * 4;   // 69632 B
    cudaFuncSetAttribute(gemm_tc, cudaFuncAttributeMaxDynamicSharedMemorySize, smemSz);

    // graph preprocessing (dinv must precede gemm epilogue)
    k_zero<<<(NN + 255) / 256, 256>>>();
    k_count<<<(NE + 255) / 256, 256>>>(dstI);
    k_scan<<<1, 1024>>>();
    k_scatter<<<(NE + 255) / 256, 256>>>(srcI, dstI);
    k_compose<<<1, 256>>>(mpW1, mpW2, mpb1, mpb2);
    k_bfrag_all<<<48, 256>>>(W1, W2, W3);

    int gemmBlocks = (NN + 127) / 128;
    int aggBlocks = (NN * 32 + 255) / 256;

    // layer 0
    gemm_tc<<<gemmBlocks, 256, smemSz>>>(x, bH, bL, h16, NN);
    k_agg<<<aggBlocks, 256>>>(h16, b1, ln1g, ln1b, bufA, 1, nullptr);
    // layer 1
    gemm_tc<<<gemmBlocks, 256, smemSz>>>(bufA, bH + 4096, bL + 4096, h16, NN);
    k_agg<<<aggBlocks, 256>>>(h16, b2, ln2g, ln2b, bufA, 1, nullptr);
    // layer 2 -> emb + fused head
    gemm_tc<<<gemmBlocks, 256, smemSz>>>(bufA, bH + 8192, bL + 8192, h16, NN);
    k_agg<<<aggBlocks, 256>>>(h16, b3, nullptr, nullptr, emb, 0, logp);
}